// round 1
// baseline (speedup 1.0000x reference)
#include <cuda_runtime.h>

// RNN_26895085207932 : Elman RNN, SEQ=2048, B=4096, IN=1, H=32 + trailing Linear(32->1)
// Strategy: warp-per-2-batches, lane = hidden unit, f32x2 packed math,
// smem double-buffered h exchange, fused output reduction.

typedef unsigned long long ull;

static constexpr int SEQ = 2048;
static constexpr int B   = 4096;
static constexpr int H   = 32;

__device__ __forceinline__ ull pack2(float lo, float hi) {
    ull r; asm("mov.b64 %0, {%1, %2};" : "=l"(r) : "f"(lo), "f"(hi)); return r;
}
__device__ __forceinline__ void unpack2(ull v, float& lo, float& hi) {
    asm("mov.b64 {%0, %1}, %2;" : "=f"(lo), "=f"(hi) : "l"(v));
}
__device__ __forceinline__ ull fma2(ull a, ull b, ull c) {
    ull d; asm("fma.rn.f32x2 %0, %1, %2, %3;" : "=l"(d) : "l"(a), "l"(b), "l"(c)); return d;
}
__device__ __forceinline__ ull add2(ull a, ull b) {
    ull d; asm("add.rn.f32x2 %0, %1, %2;" : "=l"(d) : "l"(a), "l"(b)); return d;
}
__device__ __forceinline__ ull mul2(ull a, ull b) {
    ull d; asm("mul.rn.f32x2 %0, %1, %2;" : "=l"(d) : "l"(a), "l"(b)); return d;
}
__device__ __forceinline__ ull shfl_xor2(ull v, int d) {
    unsigned lo = (unsigned)v, hi = (unsigned)(v >> 32);
    lo = __shfl_xor_sync(0xffffffffu, lo, d);
    hi = __shfl_xor_sync(0xffffffffu, hi, d);
    return ((ull)hi << 32) | (ull)lo;
}

// Accurate fast tanh: tanh(z) = 1 - 2/(exp(2z)+1).
// |z| <= ~7 mathematically (|xp|<=1.4, |W h|<=sum|w|<=5.7) -> exp(2z) <= ~1.2e6, no overflow.
// MUFU.EX2 + MUFU.RCP path: ~1e-7 abs error, safe through the 2048-step recurrence.
__device__ __forceinline__ float tanh_acc(float z) {
    float e = exp2f(z * 2.88539008177793f);   // exp(2z) = 2^(2z*log2(e)) : FMUL + MUFU.EX2
    return 1.0f - __fdividef(2.0f, e + 1.0f); // FADD + MUFU.RCP + FMUL + FFMA
}

__global__ void __launch_bounds__(32)
rnn_kernel(const float* __restrict__ x,      // (SEQ, B, 1)
           const float* __restrict__ hidden, // (1, B, H)
           const float* __restrict__ Wih,    // (H, 1)
           const float* __restrict__ bih,    // (H)
           const float* __restrict__ Whh,    // (H, H)
           const float* __restrict__ bhh,    // (H)
           const float* __restrict__ Wfc,    // (1, H)
           const float* __restrict__ bfc,    // (1)
           float* __restrict__ out)          // (SEQ, B, 1)
{
    __shared__ __align__(16) float2 hbuf[2][H]; // double-buffered hidden state (2 batches packed)

    const int j  = threadIdx.x;      // hidden unit owned by this lane
    const int bx = blockIdx.x;       // batch pair index
    const int b0 = bx * 2;

    // W_hh row j, duplicated into packed registers (same multiplier for both batches).
    ull w2[H];
#pragma unroll
    for (int k = 0; k < H; k++) {
        float w = Whh[j * H + k];
        w2[k] = pack2(w, w);
    }
    const float wih  = Wih[j];
    const float bias = bih[j] + bhh[j];
    const ull wih2   = pack2(wih, wih);
    const ull bias2  = pack2(bias, bias);
    const float wfc  = Wfc[j];
    const ull wfc2   = pack2(wfc, wfc);
    const float bfc0 = bfc[0];

    // initial hidden state
    hbuf[0][j] = make_float2(hidden[(size_t)b0 * H + j], hidden[(size_t)(b0 + 1) * H + j]);
    __syncwarp();

    // x for this batch pair: adjacent floats -> one float2 per step (broadcast LDG.64).
    const float2* xg = reinterpret_cast<const float2*>(x) + bx;  // step s at xg[s * (B/2)]
    float2* og       = reinterpret_cast<float2*>(out) + bx;

    // 4-deep x prefetch pipeline
    float2 xpipe[4];
#pragma unroll
    for (int i = 0; i < 4; i++) xpipe[i] = xg[(size_t)i * (B / 2)];

    for (int s = 0; s < SEQ; s += 4) {
#pragma unroll
        for (int u = 0; u < 4; u++) {
            const int st = s + u;
            const int p  = u & 1;          // s%4==0 starts each outer iter at buffer 0
            float2 xs = xpipe[u];
            const int sn = st + 4;
            if (sn < SEQ) xpipe[u] = xg[(size_t)sn * (B / 2)];

            // acc = x*W_ih + b_ih + b_hh  (packed over the 2 batches)
            ull acc0 = fma2(pack2(xs.x, xs.y), wih2, bias2);
            ull acc1 = 0; // bits == (+0.f, +0.f)

            // h_{t-1} @ W_hh^T, row j: broadcast LDS.128 reads, 2 accumulator chains
            const ulonglong2* hb = reinterpret_cast<const ulonglong2*>(hbuf[p]);
#pragma unroll
            for (int g = 0; g < H / 2; g++) {
                ulonglong2 hv = hb[g];
                acc0 = fma2(hv.x, w2[2 * g],     acc0);
                acc1 = fma2(hv.y, w2[2 * g + 1], acc1);
            }
            ull acc = add2(acc0, acc1);

            float zA, zB;
            unpack2(acc, zA, zB);
            const float hA = tanh_acc(zA);
            const float hB = tanh_acc(zB);

            // fused output: out_t = sum_j wfc[j] * h_t[j] + bfc  (packed butterfly)
            ull pv = mul2(pack2(hA, hB), wfc2);
#pragma unroll
            for (int d = 16; d > 0; d >>= 1) {
                pv = add2(pv, shfl_xor2(pv, d));
            }
            if (j == 0) {
                float oA, oB;
                unpack2(pv, oA, oB);
                og[(size_t)st * (B / 2)] = make_float2(oA + bfc0, oB + bfc0);
            }

            // publish h_t for next step
            hbuf[p ^ 1][j] = make_float2(hA, hB);
            __syncwarp();
        }
    }
}

extern "C" void kernel_launch(void* const* d_in, const int* in_sizes, int n_in,
                              void* d_out, int out_size) {
    const float* x      = (const float*)d_in[0];
    const float* hidden = (const float*)d_in[1];
    const float* Wih    = (const float*)d_in[2];
    const float* bih    = (const float*)d_in[3];
    const float* Whh    = (const float*)d_in[4];
    const float* bhh    = (const float*)d_in[5];
    const float* Wfc    = (const float*)d_in[6];
    const float* bfc    = (const float*)d_in[7];
    (void)in_sizes; (void)n_in; (void)out_size;

    rnn_kernel<<<B / 2, 32>>>(x, hidden, Wih, bih, Whh, bhh, Wfc, bfc, (float*)d_out);
}

// round 2
// speedup vs baseline: 1.1940x; 1.1940x over previous
#include <cuda_runtime.h>

// RNN_26895085207932 : Elman RNN, SEQ=2048, B=4096, IN=1, H=32 + Linear(32->1)
// R2: remove per-step shuffle butterfly (MIO-bound at 74.6% l1tex).
// Output partials p_j = wfc[j]*h_t[j] go to a 32-step smem ring; transposed
// reduction (lane j sums timestep base+j) once per 32 steps, off the critical path.

typedef unsigned long long ull;

static constexpr int SEQ = 2048;
static constexpr int B   = 4096;
static constexpr int H   = 32;

__device__ __forceinline__ ull pack2(float lo, float hi) {
    ull r; asm("mov.b64 %0, {%1, %2};" : "=l"(r) : "f"(lo), "f"(hi)); return r;
}
__device__ __forceinline__ void unpack2(ull v, float& lo, float& hi) {
    asm("mov.b64 {%0, %1}, %2;" : "=f"(lo), "=f"(hi) : "l"(v));
}
__device__ __forceinline__ ull fma2(ull a, ull b, ull c) {
    ull d; asm("fma.rn.f32x2 %0, %1, %2, %3;" : "=l"(d) : "l"(a), "l"(b), "l"(c)); return d;
}
__device__ __forceinline__ ull add2(ull a, ull b) {
    ull d; asm("add.rn.f32x2 %0, %1, %2;" : "=l"(d) : "l"(a), "l"(b)); return d;
}
__device__ __forceinline__ ull mul2(ull a, ull b) {
    ull d; asm("mul.rn.f32x2 %0, %1, %2;" : "=l"(d) : "l"(a), "l"(b)); return d;
}

// tanh(z) = 1 - 2/(exp(2z)+1); |z| <= ~7 so exp(2z) <= ~1.2e6, no overflow.
// FMUL + MUFU.EX2 + FADD + MUFU.RCP + FMUL + FADD: abs err ~1e-7.
__device__ __forceinline__ float tanh_acc(float z) {
    float e = exp2f(z * 2.88539008177793f);
    return 1.0f - __fdividef(2.0f, e + 1.0f);
}

__global__ void __launch_bounds__(32, 14)
rnn_kernel(const float* __restrict__ x,      // (SEQ, B, 1)
           const float* __restrict__ hidden, // (1, B, H)
           const float* __restrict__ Wih,    // (H, 1)
           const float* __restrict__ bih,    // (H)
           const float* __restrict__ Whh,    // (H, H)
           const float* __restrict__ bhh,    // (H)
           const float* __restrict__ Wfc,    // (1, H)
           const float* __restrict__ bfc,    // (1)
           float* __restrict__ out)          // (SEQ, B, 1)
{
    __shared__ __align__(16) float2 hbuf[2][H];     // double-buffered hidden state
    __shared__ __align__(16) float2 phist[32][34];  // wfc[j]*h ring; 34 => 16B-aligned rows

    const int j  = threadIdx.x;   // hidden unit owned by this lane
    const int bx = blockIdx.x;    // batch pair index
    const int b0 = bx * 2;

    // W_hh row j, duplicated into packed registers.
    ull w2[H];
#pragma unroll
    for (int k = 0; k < H; k++) {
        float w = Whh[j * H + k];
        w2[k] = pack2(w, w);
    }
    const float wih  = Wih[j];
    const float bias = bih[j] + bhh[j];
    const ull wih2   = pack2(wih, wih);
    const ull bias2  = pack2(bias, bias);
    const float wfc  = Wfc[j];
    const ull wfc2   = pack2(wfc, wfc);
    const float bfc0 = bfc[0];

    hbuf[0][j] = make_float2(hidden[(size_t)b0 * H + j], hidden[(size_t)(b0 + 1) * H + j]);
    __syncwarp();

    const float2* xg = reinterpret_cast<const float2*>(x) + bx;   // step s at xg[s*(B/2)]
    float2* og       = reinterpret_cast<float2*>(out) + bx;

    // 4-deep x prefetch pipeline
    float2 xpipe[4];
#pragma unroll
    for (int i = 0; i < 4; i++) xpipe[i] = xg[(size_t)i * (B / 2)];

    for (int base = 0; base < SEQ; base += 32) {
#pragma unroll 2
        for (int q = 0; q < 8; q++) {
#pragma unroll
            for (int u = 0; u < 4; u++) {
                const int st = base + q * 4 + u;   // current step
                const int p  = st & 1;             // read buffer parity
                float2 xs = xpipe[u];
                if (st + 4 < SEQ) xpipe[u] = xg[(size_t)(st + 4) * (B / 2)];

                // acc = x*W_ih + (b_ih + b_hh), packed over 2 batches
                ull acc0 = fma2(pack2(xs.x, xs.y), wih2, bias2);
                ull acc1 = 0; // (+0.f, +0.f)

                // h_{t-1} @ W_hh^T row j : 16 broadcast LDS.128, two fma chains
                const ulonglong2* hb = reinterpret_cast<const ulonglong2*>(hbuf[p]);
#pragma unroll
                for (int g = 0; g < H / 2; g++) {
                    ulonglong2 hv = hb[g];
                    acc0 = fma2(hv.x, w2[2 * g],     acc0);
                    acc1 = fma2(hv.y, w2[2 * g + 1], acc1);
                }
                ull acc = add2(acc0, acc1);

                float zA, zB;
                unpack2(acc, zA, zB);
                const float hA = tanh_acc(zA);
                const float hB = tanh_acc(zB);
                const ull h2 = pack2(hA, hB);

                // publish h_t (recurrence) and p_t = wfc[j]*h_t[j] (output ring)
                hbuf[p ^ 1][j] = make_float2(hA, hB);
                ull ph = mul2(h2, wfc2);
                float pA, pB;
                unpack2(ph, pA, pB);
                phist[st & 31][j] = make_float2(pA, pB);
                __syncwarp();
            }
        }

        // Transposed output reduction: lane j computes out_{base+j} =
        // sum_k phist[j][k] + bfc. Off the recurrence critical path.
        {
            const ulonglong2* pr = reinterpret_cast<const ulonglong2*>(&phist[j][0]);
            ull s0 = 0, s1 = 0, s2 = 0, s3 = 0;
#pragma unroll
            for (int g = 0; g < 8; g++) {
                ulonglong2 a = pr[2 * g];
                ulonglong2 b = pr[2 * g + 1];
                s0 = add2(s0, a.x); s1 = add2(s1, a.y);
                s2 = add2(s2, b.x); s3 = add2(s3, b.y);
            }
            ull sv = add2(add2(s0, s1), add2(s2, s3));
            float oA, oB;
            unpack2(sv, oA, oB);
            og[(size_t)(base + j) * (B / 2)] = make_float2(oA + bfc0, oB + bfc0);
            __syncwarp();  // reduction reads done before next block overwrites ring
        }
    }
}

extern "C" void kernel_launch(void* const* d_in, const int* in_sizes, int n_in,
                              void* d_out, int out_size) {
    const float* x      = (const float*)d_in[0];
    const float* hidden = (const float*)d_in[1];
    const float* Wih    = (const float*)d_in[2];
    const float* bih    = (const float*)d_in[3];
    const float* Whh    = (const float*)d_in[4];
    const float* bhh    = (const float*)d_in[5];
    const float* Wfc    = (const float*)d_in[6];
    const float* bfc    = (const float*)d_in[7];
    (void)in_sizes; (void)n_in; (void)out_size;

    rnn_kernel<<<B / 2, 32>>>(x, hidden, Wih, bih, Whh, bhh, Wfc, bfc, (float*)d_out);
}

// round 3
// speedup vs baseline: 1.1988x; 1.0041x over previous
#include <cuda_runtime.h>

// RNN_26895085207932 : Elman RNN, SEQ=2048, B=4096, IN=1, H=32 + Linear(32->1)
// R2: remove per-step shuffle butterfly (MIO-bound at 74.6% l1tex).
// Output partials p_j = wfc[j]*h_t[j] go to a 32-step smem ring; transposed
// reduction (lane j sums timestep base+j) once per 32 steps, off the critical path.

typedef unsigned long long ull;

static constexpr int SEQ = 2048;
static constexpr int B   = 4096;
static constexpr int H   = 32;

__device__ __forceinline__ ull pack2(float lo, float hi) {
    ull r; asm("mov.b64 %0, {%1, %2};" : "=l"(r) : "f"(lo), "f"(hi)); return r;
}
__device__ __forceinline__ void unpack2(ull v, float& lo, float& hi) {
    asm("mov.b64 {%0, %1}, %2;" : "=f"(lo), "=f"(hi) : "l"(v));
}
__device__ __forceinline__ ull fma2(ull a, ull b, ull c) {
    ull d; asm("fma.rn.f32x2 %0, %1, %2, %3;" : "=l"(d) : "l"(a), "l"(b), "l"(c)); return d;
}
__device__ __forceinline__ ull add2(ull a, ull b) {
    ull d; asm("add.rn.f32x2 %0, %1, %2;" : "=l"(d) : "l"(a), "l"(b)); return d;
}
__device__ __forceinline__ ull mul2(ull a, ull b) {
    ull d; asm("mul.rn.f32x2 %0, %1, %2;" : "=l"(d) : "l"(a), "l"(b)); return d;
}

// tanh(z) = 1 - 2/(exp(2z)+1); |z| <= ~7 so exp(2z) <= ~1.2e6, no overflow.
// FMUL + MUFU.EX2 + FADD + MUFU.RCP + FMUL + FADD: abs err ~1e-7.
__device__ __forceinline__ float tanh_acc(float z) {
    float e = exp2f(z * 2.88539008177793f);
    return 1.0f - __fdividef(2.0f, e + 1.0f);
}

__global__ void __launch_bounds__(32, 14)
rnn_kernel(const float* __restrict__ x,      // (SEQ, B, 1)
           const float* __restrict__ hidden, // (1, B, H)
           const float* __restrict__ Wih,    // (H, 1)
           const float* __restrict__ bih,    // (H)
           const float* __restrict__ Whh,    // (H, H)
           const float* __restrict__ bhh,    // (H)
           const float* __restrict__ Wfc,    // (1, H)
           const float* __restrict__ bfc,    // (1)
           float* __restrict__ out)          // (SEQ, B, 1)
{
    __shared__ __align__(16) float2 hbuf[2][H];     // double-buffered hidden state
    __shared__ __align__(16) float2 phist[32][34];  // wfc[j]*h ring; 34 => 16B-aligned rows

    const int j  = threadIdx.x;   // hidden unit owned by this lane
    const int bx = blockIdx.x;    // batch pair index
    const int b0 = bx * 2;

    // W_hh row j, duplicated into packed registers.
    ull w2[H];
#pragma unroll
    for (int k = 0; k < H; k++) {
        float w = Whh[j * H + k];
        w2[k] = pack2(w, w);
    }
    const float wih  = Wih[j];
    const float bias = bih[j] + bhh[j];
    const ull wih2   = pack2(wih, wih);
    const ull bias2  = pack2(bias, bias);
    const float wfc  = Wfc[j];
    const ull wfc2   = pack2(wfc, wfc);
    const float bfc0 = bfc[0];

    hbuf[0][j] = make_float2(hidden[(size_t)b0 * H + j], hidden[(size_t)(b0 + 1) * H + j]);
    __syncwarp();

    const float2* xg = reinterpret_cast<const float2*>(x) + bx;   // step s at xg[s*(B/2)]
    float2* og       = reinterpret_cast<float2*>(out) + bx;

    // 4-deep x prefetch pipeline
    float2 xpipe[4];
#pragma unroll
    for (int i = 0; i < 4; i++) xpipe[i] = xg[(size_t)i * (B / 2)];

    for (int base = 0; base < SEQ; base += 32) {
#pragma unroll 2
        for (int q = 0; q < 8; q++) {
#pragma unroll
            for (int u = 0; u < 4; u++) {
                const int st = base + q * 4 + u;   // current step
                const int p  = st & 1;             // read buffer parity
                float2 xs = xpipe[u];
                if (st + 4 < SEQ) xpipe[u] = xg[(size_t)(st + 4) * (B / 2)];

                // acc = x*W_ih + (b_ih + b_hh), packed over 2 batches
                ull acc0 = fma2(pack2(xs.x, xs.y), wih2, bias2);
                ull acc1 = 0; // (+0.f, +0.f)

                // h_{t-1} @ W_hh^T row j : 16 broadcast LDS.128, two fma chains
                const ulonglong2* hb = reinterpret_cast<const ulonglong2*>(hbuf[p]);
#pragma unroll
                for (int g = 0; g < H / 2; g++) {
                    ulonglong2 hv = hb[g];
                    acc0 = fma2(hv.x, w2[2 * g],     acc0);
                    acc1 = fma2(hv.y, w2[2 * g + 1], acc1);
                }
                ull acc = add2(acc0, acc1);

                float zA, zB;
                unpack2(acc, zA, zB);
                const float hA = tanh_acc(zA);
                const float hB = tanh_acc(zB);
                const ull h2 = pack2(hA, hB);

                // publish h_t (recurrence) and p_t = wfc[j]*h_t[j] (output ring)
                hbuf[p ^ 1][j] = make_float2(hA, hB);
                ull ph = mul2(h2, wfc2);
                float pA, pB;
                unpack2(ph, pA, pB);
                phist[st & 31][j] = make_float2(pA, pB);
                __syncwarp();
            }
        }

        // Transposed output reduction: lane j computes out_{base+j} =
        // sum_k phist[j][k] + bfc. Off the recurrence critical path.
        {
            const ulonglong2* pr = reinterpret_cast<const ulonglong2*>(&phist[j][0]);
            ull s0 = 0, s1 = 0, s2 = 0, s3 = 0;
#pragma unroll
            for (int g = 0; g < 8; g++) {
                ulonglong2 a = pr[2 * g];
                ulonglong2 b = pr[2 * g + 1];
                s0 = add2(s0, a.x); s1 = add2(s1, a.y);
                s2 = add2(s2, b.x); s3 = add2(s3, b.y);
            }
            ull sv = add2(add2(s0, s1), add2(s2, s3));
            float oA, oB;
            unpack2(sv, oA, oB);
            og[(size_t)(base + j) * (B / 2)] = make_float2(oA + bfc0, oB + bfc0);
            __syncwarp();  // reduction reads done before next block overwrites ring
        }
    }
}

extern "C" void kernel_launch(void* const* d_in, const int* in_sizes, int n_in,
                              void* d_out, int out_size) {
    const float* x      = (const float*)d_in[0];
    const float* hidden = (const float*)d_in[1];
    const float* Wih    = (const float*)d_in[2];
    const float* bih    = (const float*)d_in[3];
    const float* Whh    = (const float*)d_in[4];
    const float* bhh    = (const float*)d_in[5];
    const float* Wfc    = (const float*)d_in[6];
    const float* bfc    = (const float*)d_in[7];
    (void)in_sizes; (void)n_in; (void)out_size;

    rnn_kernel<<<B / 2, 32>>>(x, hidden, Wih, bih, Whh, bhh, Wfc, bfc, (float*)d_out);
}

// round 4
// speedup vs baseline: 1.2065x; 1.0064x over previous
#include <cuda_runtime.h>

// RNN_26895085207932 : Elman RNN, SEQ=2048, B=4096, IN=1, H=32 + Linear(32->1)
// R3: issue-bound fix — 4 independent fma2 accumulator chains (was 2, capping a
// warp at 0.5 instr/cyc during matvec) + MUFU.TANH (saves ~10 instr/step).

typedef unsigned long long ull;

static constexpr int SEQ = 2048;
static constexpr int B   = 4096;
static constexpr int H   = 32;

__device__ __forceinline__ ull pack2(float lo, float hi) {
    ull r; asm("mov.b64 %0, {%1, %2};" : "=l"(r) : "f"(lo), "f"(hi)); return r;
}
__device__ __forceinline__ void unpack2(ull v, float& lo, float& hi) {
    asm("mov.b64 {%0, %1}, %2;" : "=f"(lo), "=f"(hi) : "l"(v));
}
__device__ __forceinline__ ull fma2(ull a, ull b, ull c) {
    ull d; asm("fma.rn.f32x2 %0, %1, %2, %3;" : "=l"(d) : "l"(a), "l"(b), "l"(c)); return d;
}
__device__ __forceinline__ ull add2(ull a, ull b) {
    ull d; asm("add.rn.f32x2 %0, %1, %2;" : "=l"(d) : "l"(a), "l"(b)); return d;
}
__device__ __forceinline__ ull mul2(ull a, ull b) {
    ull d; asm("mul.rn.f32x2 %0, %1, %2;" : "=l"(d) : "l"(a), "l"(b)); return d;
}
// MUFU.TANH : 1 instr, abs err ~2^-10.8 — recurrence is contractive (rho~0.58),
// expected propagated error ~1e-4 << 1e-3 threshold.
__device__ __forceinline__ float tanh_fast(float z) {
    float r; asm("tanh.approx.f32 %0, %1;" : "=f"(r) : "f"(z)); return r;
}

__global__ void __launch_bounds__(32, 14)
rnn_kernel(const float* __restrict__ x,      // (SEQ, B, 1)
           const float* __restrict__ hidden, // (1, B, H)
           const float* __restrict__ Wih,    // (H, 1)
           const float* __restrict__ bih,    // (H)
           const float* __restrict__ Whh,    // (H, H)
           const float* __restrict__ bhh,    // (H)
           const float* __restrict__ Wfc,    // (1, H)
           const float* __restrict__ bfc,    // (1)
           float* __restrict__ out)          // (SEQ, B, 1)
{
    __shared__ __align__(16) float2 hbuf[2][H];     // double-buffered hidden state
    __shared__ __align__(16) float2 phist[32][34];  // wfc[j]*h ring (padded rows)

    const int j  = threadIdx.x;   // hidden unit owned by this lane
    const int bx = blockIdx.x;    // batch pair
    const int b0 = bx * 2;

    ull w2[H];
#pragma unroll
    for (int k = 0; k < H; k++) {
        float w = Whh[j * H + k];
        w2[k] = pack2(w, w);
    }
    const float wih  = Wih[j];
    const float bias = bih[j] + bhh[j];
    const ull wih2   = pack2(wih, wih);
    const ull bias2  = pack2(bias, bias);
    const float wfc  = Wfc[j];
    const ull wfc2   = pack2(wfc, wfc);
    const float bfc0 = bfc[0];

    hbuf[0][j] = make_float2(hidden[(size_t)b0 * H + j], hidden[(size_t)(b0 + 1) * H + j]);
    __syncwarp();

    const float2* xg = reinterpret_cast<const float2*>(x) + bx;   // step s at xg[s*(B/2)]
    float2* og       = reinterpret_cast<float2*>(out) + bx;

    float2 xpipe[4];
#pragma unroll
    for (int i = 0; i < 4; i++) xpipe[i] = xg[(size_t)i * (B / 2)];

    for (int base = 0; base < SEQ; base += 32) {
#pragma unroll 2
        for (int q = 0; q < 8; q++) {
#pragma unroll
            for (int u = 0; u < 4; u++) {
                const int st = base + q * 4 + u;
                const int p  = st & 1;
                float2 xs = xpipe[u];
                if (st + 4 < SEQ) xpipe[u] = xg[(size_t)(st + 4) * (B / 2)];

                // acc = x*W_ih + (b_ih + b_hh), packed over 2 batches
                ull acc0 = fma2(pack2(xs.x, xs.y), wih2, bias2);
                ull acc1 = 0, acc2 = 0, acc3 = 0;  // 4 independent chains

                // h_{t-1} @ W_hh^T row j : 16 broadcast LDS.128, 4 fma2 chains
                const ulonglong2* hb = reinterpret_cast<const ulonglong2*>(hbuf[p]);
#pragma unroll
                for (int g = 0; g < 8; g++) {
                    ulonglong2 ha = hb[2 * g];
                    ulonglong2 hc = hb[2 * g + 1];
                    acc0 = fma2(ha.x, w2[4 * g],     acc0);
                    acc1 = fma2(ha.y, w2[4 * g + 1], acc1);
                    acc2 = fma2(hc.x, w2[4 * g + 2], acc2);
                    acc3 = fma2(hc.y, w2[4 * g + 3], acc3);
                }
                ull acc = add2(add2(acc0, acc1), add2(acc2, acc3));

                float zA, zB;
                unpack2(acc, zA, zB);
                const float hA = tanh_fast(zA);
                const float hB = tanh_fast(zB);
                const ull h2 = pack2(hA, hB);

                hbuf[p ^ 1][j] = make_float2(hA, hB);
                ull ph = mul2(h2, wfc2);
                float pA, pB;
                unpack2(ph, pA, pB);
                phist[st & 31][j] = make_float2(pA, pB);
                __syncwarp();
            }
        }

        // Transposed output reduction (amortized over 32 steps)
        {
            const ulonglong2* pr = reinterpret_cast<const ulonglong2*>(&phist[j][0]);
            ull s0 = 0, s1 = 0, s2 = 0, s3 = 0;
#pragma unroll
            for (int g = 0; g < 8; g++) {
                ulonglong2 a = pr[2 * g];
                ulonglong2 b = pr[2 * g + 1];
                s0 = add2(s0, a.x); s1 = add2(s1, a.y);
                s2 = add2(s2, b.x); s3 = add2(s3, b.y);
            }
            ull sv = add2(add2(s0, s1), add2(s2, s3));
            float oA, oB;
            unpack2(sv, oA, oB);
            og[(size_t)(base + j) * (B / 2)] = make_float2(oA + bfc0, oB + bfc0);
            __syncwarp();
        }
    }
}

extern "C" void kernel_launch(void* const* d_in, const int* in_sizes, int n_in,
                              void* d_out, int out_size) {
    const float* x      = (const float*)d_in[0];
    const float* hidden = (const float*)d_in[1];
    const float* Wih    = (const float*)d_in[2];
    const float* bih    = (const float*)d_in[3];
    const float* Whh    = (const float*)d_in[4];
    const float* bhh    = (const float*)d_in[5];
    const float* Wfc    = (const float*)d_in[6];
    const float* bfc    = (const float*)d_in[7];
    (void)in_sizes; (void)n_in; (void)out_size;

    rnn_kernel<<<B / 2, 32>>>(x, hidden, Wih, bih, Whh, bhh, Wfc, bfc, (float*)d_out);
}